// round 1
// baseline (speedup 1.0000x reference)
#include <cuda_runtime.h>
#include <cuda_bf16.h>
#include <cstdint>

// DeployPostProcessor: per-batch top-300 of sigmoid(logits[B=256,Q=1000,C=80]),
// labels = idx % 80, qidx = idx / 80, boxes cxcywh->xyxy gathered at qidx.
// Output (float32, concatenated): labels [256*300], boxes [256*300*4], scores [256*300].

#define BATCH       256
#define NPER        80000      // 1000*80 per batch
#define N4          20000      // NPER/4
#define NCLS        80
#define TOPK        300
#define NBUCKET     16384
#define CHUNK       16         // buckets per thread in scan (16384/1024)
#define NTHREADS    1024
#define CAP         1024       // candidate capacity (sorted set size)

// monotone key for float ordering (ascending float -> ascending uint32)
__device__ __forceinline__ uint32_t fkey(float x) {
    uint32_t b = __float_as_uint(x);
    uint32_t mask = (uint32_t)((int32_t)b >> 31) | 0x80000000u;
    return b ^ mask;
}

__global__ __launch_bounds__(NTHREADS, 1)
void postproc_kernel(const float* __restrict__ logits,
                     const float* __restrict__ boxes,
                     float* __restrict__ out)
{
    extern __shared__ unsigned char smem_raw[];
    // layout: hist[16384] u32 (64KB)  -- later reused as keys[1024] u64 (8KB)
    //         S[1024] u32 (4KB) at +65536
    //         scalars at +69632
    uint32_t* hist = (uint32_t*)smem_raw;
    unsigned long long* keys = (unsigned long long*)smem_raw;   // alias of hist
    uint32_t* S = (uint32_t*)(smem_raw + NBUCKET * 4);
    uint32_t* scal = (uint32_t*)(smem_raw + NBUCKET * 4 + NTHREADS * 4);
    // scal[0] = threshold bucket, scal[1] = candidate counter

    const int tid = threadIdx.x;
    const int b   = blockIdx.x;
    const float4* lg4 = (const float4*)(logits + (size_t)b * NPER);

    // ---- init histogram ----
    #pragma unroll
    for (int i = 0; i < CHUNK; ++i)
        hist[tid + i * NTHREADS] = 0;
    if (tid == 0) { scal[1] = 0; }
    __syncthreads();

    // ---- pass 1: histogram of monotone logit keys ----
    for (int i = tid; i < N4; i += NTHREADS) {
        float4 v = lg4[i];
        atomicAdd(&hist[fkey(v.x) >> 18], 1u);
        atomicAdd(&hist[fkey(v.y) >> 18], 1u);
        atomicAdd(&hist[fkey(v.z) >> 18], 1u);
        atomicAdd(&hist[fkey(v.w) >> 18], 1u);
    }
    __syncthreads();

    // ---- chunk sums ----
    uint32_t csum = 0;
    #pragma unroll
    for (int i = 0; i < CHUNK; ++i)
        csum += hist[tid * CHUNK + i];
    S[tid] = csum;
    __syncthreads();

    // ---- inclusive suffix scan of S (Hillis-Steele) ----
    for (int off = 1; off < NTHREADS; off <<= 1) {
        uint32_t v = S[tid] + ((tid + off < NTHREADS) ? S[tid + off] : 0u);
        __syncthreads();
        S[tid] = v;
        __syncthreads();
    }

    // ---- find threshold bucket: smallest t with count(key >= t<<18) >= TOPK ----
    {
        uint32_t base = (tid == NTHREADS - 1) ? 0u : S[tid + 1];
        uint32_t mine = S[tid];
        if (base < TOPK && mine >= TOPK) {
            uint32_t running = base;
            for (int bk = tid * CHUNK + CHUNK - 1; bk >= tid * CHUNK; --bk) {
                running += hist[bk];
                if (running >= TOPK) { scal[0] = (uint32_t)bk; break; }
            }
        }
    }
    __syncthreads();

    uint32_t tbk = scal[0];
    if (tbk > 0) tbk -= 1;                 // one-bucket margin for sigmoid ties
    const uint32_t thr_key = tbk << 18;
    __syncthreads();                        // done reading hist; reuse as keys

    // ---- pass 2: collect candidates, key = (sigmoid_bits<<32) | ~index ----
    for (int i = tid; i < N4; i += NTHREADS) {
        float4 v = lg4[i];
        float vv[4] = {v.x, v.y, v.z, v.w};
        #pragma unroll
        for (int c = 0; c < 4; ++c) {
            float x = vv[c];
            if (fkey(x) >= thr_key) {
                uint32_t pos = atomicAdd(&scal[1], 1u);
                if (pos < CAP) {
                    float s = 1.0f / (1.0f + expf(-x));
                    uint32_t idx = (uint32_t)(i * 4 + c);
                    unsigned long long key =
                        ((unsigned long long)__float_as_uint(s) << 32)
                        | (unsigned long long)(0xFFFFFFFFu - idx);
                    keys[pos] = key;
                }
            }
        }
    }
    __syncthreads();

    // ---- pad to CAP ----
    uint32_t cnt = scal[1];
    if (cnt > CAP) cnt = CAP;
    for (int i = tid; i < CAP; i += NTHREADS)
        if ((uint32_t)i >= cnt) keys[i] = 0ull;
    __syncthreads();

    // ---- bitonic sort descending over CAP=1024 keys ----
    for (int k = 2; k <= CAP; k <<= 1) {
        for (int j = k >> 1; j > 0; j >>= 1) {
            int ixj = tid ^ j;
            if (ixj > tid) {
                unsigned long long a = keys[tid];
                unsigned long long c2 = keys[ixj];
                bool desc = ((tid & k) == 0);
                bool sw = desc ? (a < c2) : (a > c2);
                if (sw) { keys[tid] = c2; keys[ixj] = a; }
            }
            __syncthreads();
        }
    }

    // ---- emit top 300: labels | boxes(xyxy) | scores ----
    if (tid < TOPK) {
        unsigned long long key = keys[tid];
        uint32_t sbits = (uint32_t)(key >> 32);
        uint32_t idx   = 0xFFFFFFFFu - (uint32_t)(key & 0xFFFFFFFFull);
        float score = __uint_as_float(sbits);
        int   label = (int)(idx % NCLS);
        int   q     = (int)(idx / NCLS);

        const float4 bx = ((const float4*)boxes)[b * 1000 + q];
        float cx = bx.x, cy = bx.y, w = bx.z, h = bx.w;

        int base = b * TOPK + tid;
        out[base] = (float)label;                              // labels  [0 .. 76800)
        float* bo = out + BATCH * TOPK + (size_t)base * 4;     // boxes   [76800 .. 384000)
        bo[0] = cx - 0.5f * w;
        bo[1] = cy - 0.5f * h;
        bo[2] = cx + 0.5f * w;
        bo[3] = cy + 0.5f * h;
        out[BATCH * TOPK * 5 + base] = score;                  // scores  [384000 .. 460800)
    }
}

extern "C" void kernel_launch(void* const* d_in, const int* in_sizes, int n_in,
                              void* d_out, int out_size)
{
    const float* logits = (const float*)d_in[0];
    const float* boxes  = (const float*)d_in[1];
    float* out = (float*)d_out;

    const int smem_bytes = NBUCKET * 4 + NTHREADS * 4 + 64;   // 69,696 B
    static bool attr_set = false;
    if (!attr_set) {
        cudaFuncSetAttribute(postproc_kernel,
                             cudaFuncAttributeMaxDynamicSharedMemorySize, smem_bytes);
        attr_set = true;
    }
    postproc_kernel<<<BATCH, NTHREADS, smem_bytes>>>(logits, boxes, out);
}

// round 2
// speedup vs baseline: 1.1041x; 1.1041x over previous
#include <cuda_runtime.h>
#include <cuda_bf16.h>
#include <cstdint>

// DeployPostProcessor: per-batch top-300 of sigmoid(logits[B=256,Q=1000,C=80]),
// labels = idx % 80, qidx = idx / 80, boxes cxcywh->xyxy gathered at qidx.
// Output (float32, concatenated): labels [256*300], boxes [256*300*4], scores [256*300].

#define BATCH       256
#define NPER        80000      // 1000*80 per batch
#define N4          20000      // NPER/4
#define NCLS        80
#define TOPK        300
#define NBUCKET     16384
#define CHUNK       16         // buckets per thread in fallback scan
#define NTHREADS    1024
#define CAP         1536       // candidate capacity
#define PTHRESH     2.2999f    // static prefilter: count(x>=2.3)~858 per batch on N(0,1)

// monotone key for float ordering (ascending float -> ascending uint32)
__device__ __forceinline__ uint32_t fkey(float x) {
    uint32_t b = __float_as_uint(x);
    uint32_t mask = (uint32_t)((int32_t)b >> 31) | 0x80000000u;
    return b ^ mask;
}

__device__ __forceinline__ unsigned long long make_key(float x, uint32_t idx) {
    float s = 1.0f / (1.0f + expf(-x));
    return ((unsigned long long)__float_as_uint(s) << 32)
         | (unsigned long long)(0xFFFFFFFFu - idx);
}

__global__ __launch_bounds__(NTHREADS, 1)
void postproc_kernel(const float* __restrict__ logits,
                     const float* __restrict__ boxes,
                     float* __restrict__ out)
{
    extern __shared__ unsigned char smem_raw[];
    // layout: hist[16384] u32 (64KB, fallback only) aliased with keys[<=2048] u64
    //         S[1024] u32 at +65536
    //         scal[]   at +69632
    uint32_t* hist = (uint32_t*)smem_raw;
    unsigned long long* keys = (unsigned long long*)smem_raw;   // alias of hist
    uint32_t* S = (uint32_t*)(smem_raw + NBUCKET * 4);
    uint32_t* scal = (uint32_t*)(smem_raw + NBUCKET * 4 + NTHREADS * 4);
    // scal[0] = fallback threshold bucket, scal[1] = candidate counter

    const int tid = threadIdx.x;
    const int b   = blockIdx.x;
    const float4* lg4 = (const float4*)(logits + (size_t)b * NPER);

    if (tid == 0) scal[1] = 0;
    __syncthreads();

    // ============ fast path: single stream + static prefilter ============
    #pragma unroll 5
    for (int i = tid; i < N4; i += NTHREADS) {
        float4 v = lg4[i];
        if (v.x >= PTHRESH) {
            uint32_t pos = atomicAdd(&scal[1], 1u);
            if (pos < CAP) keys[pos] = make_key(v.x, (uint32_t)(i * 4 + 0));
        }
        if (v.y >= PTHRESH) {
            uint32_t pos = atomicAdd(&scal[1], 1u);
            if (pos < CAP) keys[pos] = make_key(v.y, (uint32_t)(i * 4 + 1));
        }
        if (v.z >= PTHRESH) {
            uint32_t pos = atomicAdd(&scal[1], 1u);
            if (pos < CAP) keys[pos] = make_key(v.z, (uint32_t)(i * 4 + 2));
        }
        if (v.w >= PTHRESH) {
            uint32_t pos = atomicAdd(&scal[1], 1u);
            if (pos < CAP) keys[pos] = make_key(v.w, (uint32_t)(i * 4 + 3));
        }
    }
    __syncthreads();
    uint32_t cnt = scal[1];

    // ============ fallback: exact histogram select (rarely taken) ============
    if (cnt < TOPK || cnt > CAP) {
        __syncthreads();
        #pragma unroll
        for (int i = 0; i < CHUNK; ++i)
            hist[tid + i * NTHREADS] = 0;
        if (tid == 0) scal[1] = 0;
        __syncthreads();

        for (int i = tid; i < N4; i += NTHREADS) {
            float4 v = lg4[i];
            atomicAdd(&hist[fkey(v.x) >> 18], 1u);
            atomicAdd(&hist[fkey(v.y) >> 18], 1u);
            atomicAdd(&hist[fkey(v.z) >> 18], 1u);
            atomicAdd(&hist[fkey(v.w) >> 18], 1u);
        }
        __syncthreads();

        uint32_t csum = 0;
        #pragma unroll
        for (int i = 0; i < CHUNK; ++i)
            csum += hist[tid * CHUNK + i];
        S[tid] = csum;
        __syncthreads();

        for (int off = 1; off < NTHREADS; off <<= 1) {
            uint32_t v = S[tid] + ((tid + off < NTHREADS) ? S[tid + off] : 0u);
            __syncthreads();
            S[tid] = v;
            __syncthreads();
        }

        {
            uint32_t base = (tid == NTHREADS - 1) ? 0u : S[tid + 1];
            uint32_t mine = S[tid];
            if (base < TOPK && mine >= TOPK) {
                uint32_t running = base;
                for (int bk = tid * CHUNK + CHUNK - 1; bk >= tid * CHUNK; --bk) {
                    running += hist[bk];
                    if (running >= TOPK) { scal[0] = (uint32_t)bk; break; }
                }
            }
        }
        __syncthreads();

        uint32_t tbk = scal[0];
        if (tbk > 0) tbk -= 1;                 // one-bucket margin for sigmoid ties
        const uint32_t thr_key = tbk << 18;
        __syncthreads();                        // done with hist; reuse as keys

        for (int i = tid; i < N4; i += NTHREADS) {
            float4 v = lg4[i];
            float vv[4] = {v.x, v.y, v.z, v.w};
            #pragma unroll
            for (int c = 0; c < 4; ++c) {
                if (fkey(vv[c]) >= thr_key) {
                    uint32_t pos = atomicAdd(&scal[1], 1u);
                    if (pos < CAP) keys[pos] = make_key(vv[c], (uint32_t)(i * 4 + c));
                }
            }
        }
        __syncthreads();
        cnt = scal[1];
        if (cnt > CAP) cnt = CAP;
    }

    // ============ dynamic bitonic sort (descending) over m = next pow2 ============
    int m = 512;
    while (m < (int)cnt) m <<= 1;              // cnt <= 1536 -> m <= 2048 (fits alias region)

    for (int i = tid; i < m; i += NTHREADS)
        if ((uint32_t)i >= cnt) keys[i] = 0ull;
    __syncthreads();

    for (int k = 2; k <= m; k <<= 1) {
        for (int j = k >> 1; j > 0; j >>= 1) {
            for (int i = tid; i < m; i += NTHREADS) {
                int ixj = i ^ j;
                if (ixj > i) {
                    unsigned long long a = keys[i];
                    unsigned long long c2 = keys[ixj];
                    bool desc = ((i & k) == 0);
                    bool sw = desc ? (a < c2) : (a > c2);
                    if (sw) { keys[i] = c2; keys[ixj] = a; }
                }
            }
            __syncthreads();
        }
    }

    // ============ emit top 300: labels | boxes(xyxy) | scores ============
    if (tid < TOPK) {
        unsigned long long key = keys[tid];
        uint32_t sbits = (uint32_t)(key >> 32);
        uint32_t idx   = 0xFFFFFFFFu - (uint32_t)(key & 0xFFFFFFFFull);
        float score = __uint_as_float(sbits);
        int   label = (int)(idx % NCLS);
        int   q     = (int)(idx / NCLS);

        const float4 bx = ((const float4*)boxes)[b * 1000 + q];
        float cx = bx.x, cy = bx.y, w = bx.z, h = bx.w;

        int base = b * TOPK + tid;
        out[base] = (float)label;                              // labels  [0 .. 76800)
        float* bo = out + BATCH * TOPK + (size_t)base * 4;     // boxes   [76800 .. 384000)
        bo[0] = cx - 0.5f * w;
        bo[1] = cy - 0.5f * h;
        bo[2] = cx + 0.5f * w;
        bo[3] = cy + 0.5f * h;
        out[BATCH * TOPK * 5 + base] = score;                  // scores  [384000 .. 460800)
    }
}

extern "C" void kernel_launch(void* const* d_in, const int* in_sizes, int n_in,
                              void* d_out, int out_size)
{
    const float* logits = (const float*)d_in[0];
    const float* boxes  = (const float*)d_in[1];
    float* out = (float*)d_out;

    const int smem_bytes = NBUCKET * 4 + NTHREADS * 4 + 64;   // 69,696 B
    static bool attr_set = false;
    if (!attr_set) {
        cudaFuncSetAttribute(postproc_kernel,
                             cudaFuncAttributeMaxDynamicSharedMemorySize, smem_bytes);
        attr_set = true;
    }
    postproc_kernel<<<BATCH, NTHREADS, smem_bytes>>>(logits, boxes, out);
}